// round 2
// baseline (speedup 1.0000x reference)
#include <cuda_runtime.h>
#include <cuda_bf16.h>
#include <math.h>

// Problem constants (fixed by the reference)
#define B_DIM 128
#define S_DIM 512
#define K_DIM 137
#define D_DIM (2 * K_DIM)      // 274
#define NCONN (K_DIM - 1)      // 136
#define WARPS_PER_BLOCK 8
#define THREADS (WARPS_PER_BLOCK * 32)
#define N_ITEMS (B_DIM * S_DIM)              // 65536
#define N_BLOCKS (N_ITEMS / WARPS_PER_BLOCK) // 8192

#define FULL_MASK 0xffffffffu

// Allocation-free scratch: per-block partials + completion ticket counter.
// Partials are written unconditionally every run -> no init kernel needed.
// Counter starts at 0 (static zero-init) and is reset to 0 by the last block.
__device__ float2   g_partials[N_BLOCKS];
__device__ unsigned g_counter;

// One warp handles one (b, s) item; single fused kernel (grid-wide reduce in
// the last block to arrive).
__global__ __launch_bounds__(THREADS) void t2p_fused_kernel(
    const float* __restrict__ pred,   // [128, 512, 274]
    const float* __restrict__ tgt,    // [128, 2, 512, 137]
    const int*   __restrict__ tlen,   // [128]
    float*       __restrict__ out)    // [3]
{
    __shared__ float    s_pose[WARPS_PER_BLOCK];
    __shared__ float    s_bone[WARPS_PER_BLOCK];
    __shared__ unsigned s_is_last;

    const int warp = threadIdx.x >> 5;
    const int lane = threadIdx.x & 31;
    const int item = blockIdx.x * WARPS_PER_BLOCK + warp;
    const int b = item >> 9;   // item / 512
    const int s = item & 511;  // item % 512

    float pose_sum = 0.0f;
    float bone_sum = 0.0f;

    const int L = __ldg(&tlen[b]);
    const bool bone_valid = (s < L);          // warp-uniform
    const bool pose_valid = (s < L - 1);      // implies s+1 <= S-1 (L <= S)

    if (bone_valid) {
        const float2* __restrict__ p2 = (const float2*)(pred + (size_t)item * D_DIM);
        const float*  __restrict__ t0 = tgt + ((size_t)(2 * b)     * S_DIM + s) * K_DIM;
        const float*  __restrict__ t1 = tgt + ((size_t)(2 * b + 1) * S_DIM + s) * K_DIM;

        // Register-resident errors: lane holds e[k] for k = lane + 32*j.
        float ex[5], ey[5];

        #pragma unroll
        for (int j = 0; j < 4; j++) {
            const int k = lane + 32 * j;
            float2 p  = __ldg(&p2[k]);
            float  a0 = __ldg(&t0[k]);
            float  a1 = __ldg(&t1[k]);
            ex[j] = p.x - a0;
            ey[j] = p.y - a1;
            if (pose_valid) {
                // next timestep rows are contiguous at +K
                pose_sum += fabsf(p.x - __ldg(&t0[k + K_DIM]))
                          + fabsf(p.y - __ldg(&t1[k + K_DIM]));
            }
        }
        // j = 4 partial tail: k = 128 + lane, lanes 0..8 (k <= 136)
        ex[4] = 0.0f; ey[4] = 0.0f;
        if (lane < 9) {
            const int k = 128 + lane;
            float2 p = __ldg(&p2[k]);
            ex[4] = p.x - __ldg(&t0[k]);
            ey[4] = p.y - __ldg(&t1[k]);
            if (pose_valid) {
                pose_sum += fabsf(p.x - __ldg(&t0[k + K_DIM]))
                          + fabsf(p.y - __ldg(&t1[k + K_DIM]));
            }
        }

        // Bone: d[k] = e[k+1] - e[k] via shuffles (no shared staging).
        // e[k+1]: lane<31 -> neighbor lane, same j; lane==31 -> lane 0, j+1.
        #pragma unroll
        for (int j = 0; j < 4; j++) {
            float nx_dn = __shfl_down_sync(FULL_MASK, ex[j], 1);
            float ny_dn = __shfl_down_sync(FULL_MASK, ey[j], 1);
            float nx_w0 = __shfl_sync(FULL_MASK, ex[j + 1], 0);
            float ny_w0 = __shfl_sync(FULL_MASK, ey[j + 1], 0);
            float nx = (lane == 31) ? nx_w0 : nx_dn;
            float ny = (lane == 31) ? ny_w0 : ny_dn;
            float dx = nx - ex[j];
            float dy = ny - ey[j];
            bone_sum = fmaf(dx, dx, bone_sum);
            bone_sum = fmaf(dy, dy, bone_sum);
        }
        {   // j = 4: diffs for k = 128..135 -> lanes 0..7
            float nx_dn = __shfl_down_sync(FULL_MASK, ex[4], 1);
            float ny_dn = __shfl_down_sync(FULL_MASK, ey[4], 1);
            if (lane < 8) {
                float dx = nx_dn - ex[4];
                float dy = ny_dn - ey[4];
                bone_sum = fmaf(dx, dx, bone_sum);
                bone_sum = fmaf(dy, dy, bone_sum);
            }
        }
    }

    // Warp reduce
    #pragma unroll
    for (int o = 16; o > 0; o >>= 1) {
        pose_sum += __shfl_xor_sync(FULL_MASK, pose_sum, o);
        bone_sum += __shfl_xor_sync(FULL_MASK, bone_sum, o);
    }
    if (lane == 0) {
        s_pose[warp] = pose_sum;
        s_bone[warp] = bone_sum;
    }
    __syncthreads();

    // Block partial + completion ticket
    if (threadIdx.x == 0) {
        float ps = 0.0f, bs = 0.0f;
        #pragma unroll
        for (int w = 0; w < WARPS_PER_BLOCK; w++) {
            ps += s_pose[w];
            bs += s_bone[w];
        }
        g_partials[blockIdx.x] = make_float2(ps, bs);
        __threadfence();
        unsigned old = atomicAdd(&g_counter, 1u);
        s_is_last = (old == (unsigned)(gridDim.x - 1));
    }
    __syncthreads();

    if (!s_is_last) return;

    // ---- Last block: grid-wide final reduction + loss math ----
    __threadfence();  // acquire: make all partials visible

    double dp = 0.0, db = 0.0;
    for (int i = threadIdx.x; i < N_BLOCKS; i += THREADS) {
        float2 v = g_partials[i];
        dp += (double)v.x;
        db += (double)v.y;
    }
    #pragma unroll
    for (int o = 16; o > 0; o >>= 1) {
        dp += __shfl_xor_sync(FULL_MASK, dp, o);
        db += __shfl_xor_sync(FULL_MASK, db, o);
    }
    __shared__ double r_p[WARPS_PER_BLOCK];
    __shared__ double r_b[WARPS_PER_BLOCK];
    __shared__ int    s_len[WARPS_PER_BLOCK];
    if (lane == 0) {
        r_p[warp] = dp;
        r_b[warp] = db;
    }
    // target_length sum: 128 ints, 4 per lane of each warp is overkill;
    // let each warp sum a 16-element slice via lane<16.
    {
        int lsum = 0;
        int idx = warp * 16 + lane;
        if (lane < 16) lsum = __ldg(&tlen[idx]);
        #pragma unroll
        for (int o = 16; o > 0; o >>= 1)
            lsum += __shfl_xor_sync(FULL_MASK, lsum, o);
        if (lane == 0) s_len[warp] = lsum;
    }
    __syncthreads();

    if (threadIdx.x == 0) {
        double pose_acc = 0.0, bone_acc = 0.0;
        int len_total = 0;
        #pragma unroll
        for (int w = 0; w < WARPS_PER_BLOCK; w++) {
            pose_acc  += r_p[w];
            bone_acc  += r_b[w];
            len_total += s_len[w];
        }
        double mask_sum = (double)len_total;               // sum(L)
        double pose_den = (double)(len_total - B_DIM);     // sum(L-1)

        double pose_loss = pose_acc / (double)D_DIM / pose_den;
        double bone_loss = bone_acc * 0.5 / ((double)NCONN + 1e-8) / mask_sum;
        double total     = pose_loss + 0.1 * bone_loss;

        out[0] = (float)total;
        out[1] = (float)pose_loss;
        out[2] = (float)bone_loss;

        g_counter = 0;  // reset for next graph replay
    }
}

extern "C" void kernel_launch(void* const* d_in, const int* in_sizes, int n_in,
                              void* d_out, int out_size) {
    const float* pred = (const float*)d_in[0];   // [128, 512, 274] f32
    const float* tgt  = (const float*)d_in[1];   // [128, 2, 512, 137] f32
    const int*   tlen = (const int*)d_in[2];     // [128] i32
    float* out = (float*)d_out;                  // [3] f32: total, pose, bone

    t2p_fused_kernel<<<N_BLOCKS, THREADS>>>(pred, tgt, tlen, out);
}